// round 16
// baseline (speedup 1.0000x reference)
#include <cuda_runtime.h>
#include <cstdint>

#define NB 16      // batch
#define NS 512     // seq
#define NH 384     // hidden
#define NL 2000    // max_mel_len
#define NBINS 256
#define H4 (NH/4)  // 96 float4 per row

#define TR 16                       // tile rows per CTA (125 tiles per batch row)

// scratch (no allocation allowed in kernel_launch)
__device__ int    g_seg[NB * NL];
__device__ int    g_mellen[NB];
__device__ float4 g_comb[NB * H4];   // pemb[pi_b] + eemb[ei_b]

// One block per batch row, 512 threads. Two block barriers total.
__global__ void __launch_bounds__(NS) prep_kernel(
    const float* __restrict__ log_duration,
    const float* __restrict__ pitch,
    const float* __restrict__ energy,
    const float4* __restrict__ pemb,
    const float4* __restrict__ eemb,
    float* __restrict__ out_tail, int write_tail)
{
    const int b    = blockIdx.x;
    const int tid  = threadIdx.x;
    const int warp = tid >> 5;
    const int lane = tid & 31;

    __shared__ int   wsum[16];
    __shared__ float wp[16], we[16];
    __shared__ int   s_pe[2];        // pitch idx, energy idx

    // ---- phase A: duration + warp scan, pitch/energy warp reductions ----
    const float ld = log_duration[b * NS + tid];
    const int d = (int)fmaxf(rintf(expf(ld) - 1.0f), 0.0f);

    int x = d;
    #pragma unroll
    for (int off = 1; off < 32; off <<= 1) {
        int y = __shfl_up_sync(0xffffffffu, x, off);
        if (lane >= off) x += y;
    }
    if (lane == 31) wsum[warp] = x;

    float p = pitch[b * NS + tid];
    float e = energy[b * NS + tid];
    #pragma unroll
    for (int off = 16; off > 0; off >>= 1) {
        p += __shfl_xor_sync(0xffffffffu, p, off);
        e += __shfl_xor_sync(0xffffffffu, e, off);
    }
    if (lane == 0) { wp[warp] = p; we[warp] = e; }
    __syncthreads();                               // barrier 1

    // ---- phase B: warp 0 scans warp sums; warp 1 finalizes means ----
    if (warp == 0 && lane < 16) {
        int v = wsum[lane];
        #pragma unroll
        for (int off = 1; off < 16; off <<= 1) {
            int y = __shfl_up_sync(0x0000ffffu, v, off);
            if (lane >= off) v += y;
        }
        wsum[lane] = v;
    } else if (warp == 1 && lane < 2) {
        const float* src = (lane == 0) ? wp : we;
        float s = 0.f;
        #pragma unroll
        for (int i = 0; i < 16; i++) s += src[i];
        s_pe[lane] = min(max((int)(s * (1.0f / NS)), 0), NBINS - 1);
    }
    __syncthreads();                               // barrier 2

    const int cum   = x + (warp ? wsum[warp - 1] : 0);
    const int start = cum - d;
    const int total = wsum[15];
    const int ml    = min(total, NL);

    if (tid == 0) {
        g_mellen[b] = ml;
        if (write_tail) out_tail[b] = (float)ml;
    }

    // combined embedding row: comb = pemb[pi] + eemb[ei]
    if (tid < H4) {
        float4 pv = pemb[s_pe[0] * H4 + tid];
        float4 ev = eemb[s_pe[1] * H4 + tid];
        pv.x += ev.x; pv.y += ev.y; pv.z += ev.z; pv.w += ev.w;
        g_comb[b * H4 + tid] = pv;
    }

    // segment scatter (no init: expand masks rows >= mellen)
    const int end = min(cum, NL);
    for (int l = start; l < end; ++l) g_seg[b * NL + l] = tid;

    // all writes done -> let dependent (expand) grid proceed
    asm volatile("griddepcontrol.launch_dependents;" ::: "memory");
}

// grid (125, 16), block (96, 4). Each thread: column q, 4 consecutive rows.
// Minimal critical path: no smem, no barrier, no TMA. Front-batched gather
// loads, fmaf mask, streaming (evict-first) direct stores. PDL overlap.
__global__ void __launch_bounds__(384) expand_kernel(
    const float4* __restrict__ enc,
    float4* __restrict__ out)
{
    const int q  = threadIdx.x;                 // 0..95
    const int yy = threadIdx.y;                 // 0..3
    const int b  = blockIdx.y;                  // 0..15
    const int l0 = blockIdx.x * TR;             // tile base row
    const int r0 = yy * 4;                      // my 4 consecutive rows

    // prep-independent address setup (overlaps with prep via PDL)
    const float4* __restrict__ encb = enc + b * (NS * H4);
    const int* __restrict__ segp = g_seg + b * NL + l0 + r0;
    float4* const outp = out + (size_t)(b * NL + l0 + r0) * H4 + q;

    // wait for prep grid's writes to be visible
    asm volatile("griddepcontrol.wait;" ::: "memory");

    const int ml = g_mellen[b];
    const int4 s4 = *(const int4*)segp;
    const float4 c = g_comb[b * H4 + q];

    const int sc[4] = { s4.x, s4.y, s4.z, s4.w };

    // front-batched unconditional gather loads (clamped addresses)
    float4 ev[4];
    #pragma unroll
    for (int i = 0; i < 4; i++) {
        const int s = min(max(sc[i], 0), NS - 1);
        ev[i] = __ldg(&encb[s * H4 + q]);
    }

    // masked add + streaming stores (output never re-read: evict-first)
    #pragma unroll
    for (int i = 0; i < 4; i++) {
        const float m = (l0 + r0 + i < ml) ? 1.0f : 0.0f;
        float4 v;
        v.x = fmaf(m, ev[i].x, c.x);
        v.y = fmaf(m, ev[i].y, c.y);
        v.z = fmaf(m, ev[i].z, c.z);
        v.w = fmaf(m, ev[i].w, c.w);
        __stcs(&outp[i * H4], v);
    }
}

extern "C" void kernel_launch(void* const* d_in, const int* in_sizes, int n_in,
                              void* d_out, int out_size)
{
    const float* enc   = (const float*)d_in[0];  // (B,S,H)
    const float* ldur  = (const float*)d_in[1];  // (B,S)
    const float* pitch = (const float*)d_in[2];  // (B,S)
    const float* energ = (const float*)d_in[3];  // (B,S)
    const float* pemb  = (const float*)d_in[4];  // (256,H)
    const float* eemb  = (const float*)d_in[5];  // (256,H)

    float* out = (float*)d_out;
    const int main_elems = NB * NL * NH;
    const int write_tail = (out_size >= main_elems + NB) ? 1 : 0;

    prep_kernel<<<NB, NS>>>(ldur, pitch, energ,
                            (const float4*)pemb, (const float4*)eemb,
                            out + main_elems, write_tail);

    // expand with Programmatic Dependent Launch: overlaps with prep
    cudaLaunchConfig_t cfg = {};
    cfg.gridDim  = dim3(NL / TR, NB);   // 125 x 16
    cfg.blockDim = dim3(96, 4);
    cfg.stream   = 0;
    cudaLaunchAttribute attr[1];
    attr[0].id = cudaLaunchAttributeProgrammaticStreamSerialization;
    attr[0].val.programmaticStreamSerializationAllowed = 1;
    cfg.attrs = attr;
    cfg.numAttrs = 1;
    cudaLaunchKernelEx(&cfg, expand_kernel, (const float4*)enc, (float4*)out);
}

// round 17
// speedup vs baseline: 1.0173x; 1.0173x over previous
#include <cuda_runtime.h>
#include <cstdint>

#define NB 16      // batch
#define NS 512     // seq
#define NH 384     // hidden
#define NL 2000    // max_mel_len
#define NBINS 256
#define H4 (NH/4)  // 96 float4 per row

#define TR 16                       // tile rows per CTA (125 tiles per batch row)

// scratch (no allocation allowed in kernel_launch)
__device__ int    g_seg[NB * NL];
__device__ int    g_mellen[NB];
__device__ float4 g_comb[NB * H4];   // pemb[pi_b] + eemb[ei_b]

// One block per batch row, 512 threads. Two block barriers total.
__global__ void __launch_bounds__(NS) prep_kernel(
    const float* __restrict__ log_duration,
    const float* __restrict__ pitch,
    const float* __restrict__ energy,
    const float4* __restrict__ pemb,
    const float4* __restrict__ eemb,
    float* __restrict__ out_tail, int write_tail)
{
    const int b    = blockIdx.x;
    const int tid  = threadIdx.x;
    const int warp = tid >> 5;
    const int lane = tid & 31;

    __shared__ int   wsum[16];
    __shared__ float wp[16], we[16];
    __shared__ int   s_pe[2];        // pitch idx, energy idx

    // ---- phase A: duration + warp scan, pitch/energy warp reductions ----
    const float ld = log_duration[b * NS + tid];
    const int d = (int)fmaxf(rintf(expf(ld) - 1.0f), 0.0f);

    int x = d;
    #pragma unroll
    for (int off = 1; off < 32; off <<= 1) {
        int y = __shfl_up_sync(0xffffffffu, x, off);
        if (lane >= off) x += y;
    }
    if (lane == 31) wsum[warp] = x;

    float p = pitch[b * NS + tid];
    float e = energy[b * NS + tid];
    #pragma unroll
    for (int off = 16; off > 0; off >>= 1) {
        p += __shfl_xor_sync(0xffffffffu, p, off);
        e += __shfl_xor_sync(0xffffffffu, e, off);
    }
    if (lane == 0) { wp[warp] = p; we[warp] = e; }
    __syncthreads();                               // barrier 1

    // ---- phase B: warp 0 scans warp sums; warp 1 finalizes means ----
    if (warp == 0 && lane < 16) {
        int v = wsum[lane];
        #pragma unroll
        for (int off = 1; off < 16; off <<= 1) {
            int y = __shfl_up_sync(0x0000ffffu, v, off);
            if (lane >= off) v += y;
        }
        wsum[lane] = v;
    } else if (warp == 1 && lane < 2) {
        const float* src = (lane == 0) ? wp : we;
        float s = 0.f;
        #pragma unroll
        for (int i = 0; i < 16; i++) s += src[i];
        s_pe[lane] = min(max((int)(s * (1.0f / NS)), 0), NBINS - 1);
    }
    __syncthreads();                               // barrier 2

    const int cum   = x + (warp ? wsum[warp - 1] : 0);
    const int start = cum - d;
    const int total = wsum[15];
    const int ml    = min(total, NL);

    if (tid == 0) {
        g_mellen[b] = ml;
        if (write_tail) out_tail[b] = (float)ml;
    }

    // combined embedding row: comb = pemb[pi] + eemb[ei]
    if (tid < H4) {
        float4 pv = pemb[s_pe[0] * H4 + tid];
        float4 ev = eemb[s_pe[1] * H4 + tid];
        pv.x += ev.x; pv.y += ev.y; pv.z += ev.z; pv.w += ev.w;
        g_comb[b * H4 + tid] = pv;
    }

    // tail init: rows >= ml get seg 0 (any valid index; masked to comb later)
    for (int l = ml + tid; l < NL; l += NS) g_seg[b * NL + l] = 0;

    // segment scatter for valid rows
    const int end = min(cum, NL);
    for (int l = start; l < end; ++l) g_seg[b * NL + l] = tid;
}

// grid (125, 16), block (96, 4). Each thread: column q, 4 consecutive rows.
// Minimal critical path: no smem, no barrier, no TMA, no clamp (prep
// guarantees valid seg everywhere). Front-batched gather loads, fmaf mask,
// streaming (evict-first) direct stores.
__global__ void __launch_bounds__(384) expand_kernel(
    const float4* __restrict__ enc,
    float4* __restrict__ out)
{
    const int q  = threadIdx.x;                 // 0..95
    const int yy = threadIdx.y;                 // 0..3
    const int b  = blockIdx.y;                  // 0..15
    const int l0 = blockIdx.x * TR;             // tile base row
    const int r0 = yy * 4;                      // my 4 consecutive rows

    const int ml = g_mellen[b];
    const int4 s4 = *(const int4*)(g_seg + b * NL + l0 + r0);
    const float4 c = g_comb[b * H4 + q];
    const float4* __restrict__ encb = enc + b * (NS * H4);

    const int sc[4] = { s4.x, s4.y, s4.z, s4.w };

    // front-batched unconditional gather loads (seg always valid)
    float4 ev[4];
    #pragma unroll
    for (int i = 0; i < 4; i++)
        ev[i] = __ldg(&encb[sc[i] * H4 + q]);

    // masked add + streaming stores (output never re-read: evict-first)
    float4* const outp = out + (size_t)(b * NL + l0 + r0) * H4 + q;
    #pragma unroll
    for (int i = 0; i < 4; i++) {
        const float m = (l0 + r0 + i < ml) ? 1.0f : 0.0f;
        float4 v;
        v.x = fmaf(m, ev[i].x, c.x);
        v.y = fmaf(m, ev[i].y, c.y);
        v.z = fmaf(m, ev[i].z, c.z);
        v.w = fmaf(m, ev[i].w, c.w);
        __stcs(&outp[i * H4], v);
    }
}

extern "C" void kernel_launch(void* const* d_in, const int* in_sizes, int n_in,
                              void* d_out, int out_size)
{
    const float* enc   = (const float*)d_in[0];  // (B,S,H)
    const float* ldur  = (const float*)d_in[1];  // (B,S)
    const float* pitch = (const float*)d_in[2];  // (B,S)
    const float* energ = (const float*)d_in[3];  // (B,S)
    const float* pemb  = (const float*)d_in[4];  // (256,H)
    const float* eemb  = (const float*)d_in[5];  // (256,H)

    float* out = (float*)d_out;
    const int main_elems = NB * NL * NH;
    const int write_tail = (out_size >= main_elems + NB) ? 1 : 0;

    prep_kernel<<<NB, NS>>>(ldur, pitch, energ,
                            (const float4*)pemb, (const float4*)eemb,
                            out + main_elems, write_tail);

    dim3 grid(NL / TR, NB);      // 125 x 16 = 2000 CTAs
    dim3 block(96, 4);
    expand_kernel<<<grid, block>>>((const float4*)enc, (float4*)out);
}